// round 1
// baseline (speedup 1.0000x reference)
#include <cuda_runtime.h>

// LIF recurrence: v = tau*v + (1-tau)*x ; s = (v > vth) ; v -= s*vth (reset=0)
// B=64, T=256, U=1024 fp32. Parallel over (b,u); serial over t in registers.
// Memory-bound: 134MB total traffic, HBM floor ~17us.

#define TAU   0.25f
#define OMT   0.75f   // 1 - TAU
#define VTH   1.0f
#define T_LEN 256
#define U_LEN 1024

__global__ __launch_bounds__(128)
void lif_kernel(const float* __restrict__ in, float* __restrict__ out, int nPairs) {
    const int gid = blockIdx.x * blockDim.x + threadIdx.x;  // one per float2 (2 units)
    if (gid >= nPairs) return;

    const int U2 = U_LEN / 2;
    const int b  = gid / U2;
    const int u2 = gid - b * U2;

    const float2* __restrict__ ip =
        reinterpret_cast<const float2*>(in)  + (size_t)b * T_LEN * U2 + u2;
    float2* __restrict__ op =
        reinterpret_cast<float2*>(out) + (size_t)b * T_LEN * U2 + u2;

    float vx = 0.0f, vy = 0.0f;

    #pragma unroll 8
    for (int t = 0; t < T_LEN; ++t) {
        float2 x = ip[(size_t)t * U2];          // address independent of v -> MLP-friendly
        vx = fmaf(TAU, vx, OMT * x.x);          // leaky integrate
        vy = fmaf(TAU, vy, OMT * x.y);
        float sx = (vx > VTH) ? 1.0f : 0.0f;    // fire
        float sy = (vy > VTH) ? 1.0f : 0.0f;
        vx = fmaf(sx, -VTH, vx);                // soft reset (reset value = 0)
        vy = fmaf(sy, -VTH, vy);
        float2 s; s.x = sx; s.y = sy;
        op[(size_t)t * U2] = s;
    }
}

extern "C" void kernel_launch(void* const* d_in, const int* in_sizes, int n_in,
                              void* d_out, int out_size) {
    const float* in = (const float*)d_in[0];
    float* out = (float*)d_out;

    const int total  = in_sizes[0];            // B*T*U
    const int nPairs = total / (T_LEN * U_LEN) * (U_LEN / 2);  // B * U/2

    const int block = 128;
    const int grid  = (nPairs + block - 1) / block;            // 256 blocks
    lif_kernel<<<grid, block>>>(in, out, nPairs);
}

// round 3
// speedup vs baseline: 1.2898x; 1.2898x over previous
#include <cuda_runtime.h>

// LIF recurrence, B=64 T=256 U=1024 fp32.
// Parallel over (b,u) lane-pairs; serial over t in registers.
// Double-buffered software pipeline: D loads in flight while computing
// previous chunk -> 32768 threads * 16 * 8B = 4MB outstanding (HBM needs ~2.4MB).

#define T_LEN 256
#define U2    512          // U/2 float2 lanes per row
#define D     16           // pipeline depth (chunk of t-steps)

__global__ __launch_bounds__(32)
void lif_kernel(const float2* __restrict__ in, float2* __restrict__ out) {
    const int gid = blockIdx.x * blockDim.x + threadIdx.x;   // 0..32767
    const int b   = gid >> 9;          // / U2
    const int u2  = gid & (U2 - 1);

    const float2* __restrict__ ip = in  + (size_t)b * T_LEN * U2 + u2;
    float2*       __restrict__ op = out + (size_t)b * T_LEN * U2 + u2;

    float vx = 0.0f, vy = 0.0f;
    float2 cur[D], nxt[D];

    #pragma unroll
    for (int i = 0; i < D; ++i) cur[i] = ip[(size_t)i * U2];

    #pragma unroll 1
    for (int t0 = 0; t0 < T_LEN; t0 += D) {
        const int tn = t0 + D;
        if (tn < T_LEN) {
            #pragma unroll
            for (int i = 0; i < D; ++i) nxt[i] = ip[(size_t)(tn + i) * U2];
        }
        #pragma unroll
        for (int i = 0; i < D; ++i) {
            float2 x = cur[i];
            vx = fmaf(0.25f, vx, 0.75f * x.x);        // leaky integrate
            vy = fmaf(0.25f, vy, 0.75f * x.y);
            float sx = (vx > 1.0f) ? 1.0f : 0.0f;     // fire (vth = 1)
            float sy = (vy > 1.0f) ? 1.0f : 0.0f;
            vx -= sx;                                 // soft reset (reset = 0)
            vy -= sy;
            op[(size_t)(t0 + i) * U2] = make_float2(sx, sy);
        }
        #pragma unroll
        for (int i = 0; i < D; ++i) cur[i] = nxt[i];
    }
}

extern "C" void kernel_launch(void* const* d_in, const int* in_sizes, int n_in,
                              void* d_out, int out_size) {
    const float2* in  = (const float2*)d_in[0];
    float2*       out = (float2*)d_out;

    const int total  = in_sizes[0];                          // B*T*U
    const int nPairs = total / 2;                            // float2 elements
    const int lanes  = nPairs / T_LEN;                       // B * U2 = 32768

    const int block = 32;
    const int grid  = (lanes + block - 1) / block;           // 1024 blocks
    lif_kernel<<<grid, block>>>(in, out);
}

// round 4
// speedup vs baseline: 1.3743x; 1.0655x over previous
#include <cuda_runtime.h>

// LIF recurrence, B=64 T=256 U=1024 fp32.
// Parallel over (b,u) lane-pairs; serial over t in registers.
// Ping-pong software pipeline, depth D=32: ~8MB of loads nominally in flight
// chip-wide, no inter-chunk copy/drain bubble.

#define T_LEN   256
#define U2      512          // U/2 float2 lanes per row
#define D       32           // chunk of t-steps per buffer
#define NCHUNK  (T_LEN / D)  // 8

__device__ __forceinline__ void lif_chunk(const float2* __restrict__ buf,
                                          float2* __restrict__ op, int t0,
                                          float& vx, float& vy) {
    #pragma unroll
    for (int i = 0; i < D; ++i) {
        float2 x = buf[i];
        float nvx = fmaf(0.25f, vx, 0.75f * x.x);   // leaky integrate
        float nvy = fmaf(0.25f, vy, 0.75f * x.y);
        float sx = (nvx > 1.0f) ? 1.0f : 0.0f;      // fire (vth = 1)
        float sy = (nvy > 1.0f) ? 1.0f : 0.0f;
        vx = nvx - sx;                              // soft reset (reset = 0)
        vy = nvy - sy;
        op[(size_t)(t0 + i) * U2] = make_float2(sx, sy);
    }
}

__global__ __launch_bounds__(32)
void lif_kernel(const float2* __restrict__ in, float2* __restrict__ out) {
    const int gid = blockIdx.x * blockDim.x + threadIdx.x;   // 0..32767
    const int b   = gid >> 9;          // / U2
    const int u2  = gid & (U2 - 1);

    const float2* __restrict__ ip = in  + (size_t)b * T_LEN * U2 + u2;
    float2*       __restrict__ op = out + (size_t)b * T_LEN * U2 + u2;

    float vx = 0.0f, vy = 0.0f;
    float2 bufA[D], bufB[D];

    // prime chunk 0 into A
    #pragma unroll
    for (int i = 0; i < D; ++i) bufA[i] = ip[(size_t)i * U2];

    #pragma unroll 1
    for (int c = 0; c < NCHUNK; c += 2) {
        // issue loads for chunk c+1 into B (overlaps wait on A)
        if (c + 1 < NCHUNK) {
            const size_t base = (size_t)(c + 1) * D * U2;
            #pragma unroll
            for (int i = 0; i < D; ++i) bufB[i] = ip[base + (size_t)i * U2];
        }
        lif_chunk(bufA, op, c * D, vx, vy);

        // issue loads for chunk c+2 into A (overlaps wait on B)
        if (c + 2 < NCHUNK) {
            const size_t base = (size_t)(c + 2) * D * U2;
            #pragma unroll
            for (int i = 0; i < D; ++i) bufA[i] = ip[base + (size_t)i * U2];
        }
        if (c + 1 < NCHUNK)
            lif_chunk(bufB, op, (c + 1) * D, vx, vy);
    }
}

extern "C" void kernel_launch(void* const* d_in, const int* in_sizes, int n_in,
                              void* d_out, int out_size) {
    const float2* in  = (const float2*)d_in[0];
    float2*       out = (float2*)d_out;

    const int total = in_sizes[0];                  // B*T*U
    const int lanes = total / 2 / T_LEN;            // B * U2 = 32768

    const int block = 32;
    const int grid  = (lanes + block - 1) / block;  // 1024 blocks
    lif_kernel<<<grid, block>>>(in, out);
}

// round 5
// speedup vs baseline: 1.8331x; 1.3339x over previous
#include <cuda_runtime.h>

// LIF recurrence, B=64 T=256 U=1024 fp32.
// Time-segmented: T split into 4 segments of 64; each thread warms up 24 steps
// (tau=0.25 => state error ~1e-14 at segment start, below fp32 ulp).
// 4x concurrency (131072 threads, ~28 warps/SM) to break the latency bound.
// Warmup re-reads hit L2 (input resident across replays) -> DRAM traffic unchanged.

#define T_LEN 256
#define U2    512            // U/2 float2 lanes
#define SEG   64
#define W     24
#define NSEG  (T_LEN / SEG)  // 4
#define D     8              // t-steps per chunk
#define NWCH  (W / D)        // 3 warmup chunks
#define NCH   (NWCH + SEG / D)  // 11 chunks total

__global__ __launch_bounds__(128, 7)
void lif_kernel(const float2* __restrict__ in, float2* __restrict__ out) {
    const int gid = blockIdx.x * blockDim.x + threadIdx.x;   // 0..131071
    const int u2  = gid & (U2 - 1);
    const int rs  = gid >> 9;
    const int seg = rs & (NSEG - 1);
    const int b   = rs >> 2;

    const float2* __restrict__ ip = in  + (size_t)b * T_LEN * U2 + u2;
    float2*       __restrict__ op = out + (size_t)b * T_LEN * U2 + u2;

    const int t0 = seg * SEG;
    const int ts = (seg == 0) ? 0 : (t0 - W);   // warmup start (seg0 reads [0,W), discarded)

    float vx = 0.f, vy = 0.f;
    float2 A[D], B[D];

    // chunk k start time: warmup chunks from ts, main chunks from t0
    #define CH_T(k) (((k) < NWCH) ? (ts + (k) * D) : (t0 + ((k) - NWCH) * D))

    #define LOADCH(buf, tstart) do {                                   \
        _Pragma("unroll")                                              \
        for (int i = 0; i < D; ++i)                                    \
            (buf)[i] = ip[(size_t)((tstart) + i) * U2];                \
    } while (0)

    #define PROCCH(buf, k) do {                                        \
        _Pragma("unroll")                                              \
        for (int i = 0; i < D; ++i) {                                  \
            float2 x = (buf)[i];                                       \
            vx = fmaf(0.25f, vx, 0.75f * x.x);                         \
            vy = fmaf(0.25f, vy, 0.75f * x.y);                         \
            float sx = (vx > 1.0f) ? 1.0f : 0.0f;                      \
            float sy = (vy > 1.0f) ? 1.0f : 0.0f;                      \
            vx -= sx; vy -= sy;                                        \
            if ((k) >= NWCH)                                           \
                __stcs(&op[(size_t)(CH_T(k) + i) * U2],                \
                       make_float2(sx, sy));                           \
        }                                                              \
        if ((k) == NWCH - 1 && seg == 0) { vx = 0.f; vy = 0.f; }       \
    } while (0)

    // prime ping-pong
    LOADCH(A, CH_T(0));
    LOADCH(B, CH_T(1));

    #pragma unroll
    for (int k = 0; k < NCH; k += 2) {
        PROCCH(A, k);
        if (k + 2 < NCH) LOADCH(A, CH_T(k + 2));
        if (k + 1 < NCH) PROCCH(B, k + 1);
        if (k + 3 < NCH) LOADCH(B, CH_T(k + 3));
    }

    #undef CH_T
    #undef LOADCH
    #undef PROCCH
}

extern "C" void kernel_launch(void* const* d_in, const int* in_sizes, int n_in,
                              void* d_out, int out_size) {
    const float2* in  = (const float2*)d_in[0];
    float2*       out = (float2*)d_out;

    const int total   = in_sizes[0];                 // B*T*U
    const int lanes   = total / 2 / T_LEN;           // B*U2 = 32768
    const int threads = lanes * NSEG;                // 131072

    const int block = 128;
    const int grid  = threads / block;               // 1024
    lif_kernel<<<grid, block>>>(in, out);
}